// round 1
// baseline (speedup 1.0000x reference)
#include <cuda_runtime.h>
#include <math.h>

// Problem constants
#define IMG_H   128
#define IMG_W   128
#define NB      4
#define IMG     (IMG_H * IMG_W)          // 16384
#define NPIX    (NB * IMG)               // 65536
#define NINT    1000
#define K3_BLOCKS 64
#define SM_STRIDE 129                    // padded row stride (conflict-free rows & cols)
#define SMEM_BYTES (2 * IMG_H * SM_STRIDE * sizeof(float))  // img + hsum = ~132KB

// Device scratch (static allocation — no cudaMalloc allowed)
__device__ float g_distP[NPIX];
__device__ float g_distT[NPIX];
__device__ float g_mn[NB], g_mx[NB], g_ws[NB];
__device__ float g_lo, g_dx, g_wmse;
__device__ int   g_cnt[K3_BLOCKS];

// ---------------------------------------------------------------------------
// k1: per-image box-mean distances (separable 9-tap sliding window),
//     per-block min/max of distances and wmse partial sum. Deterministic.
// grid = NB blocks, 256 threads, dynamic smem = img[128][129] + hs[128][129]
// ---------------------------------------------------------------------------
__global__ void k1_dist(const float* __restrict__ pred, const float* __restrict__ tgt) {
    extern __shared__ float sm[];
    float* img = sm;
    float* hs  = sm + IMG_H * SM_STRIDE;

    const int b   = blockIdx.x;
    const int tid = threadIdx.x;
    const float* P = pred + b * IMG;
    const float* T = tgt  + b * IMG;

    float mn = INFINITY, mx = -INFINITY, wsum = 0.0f;

    #pragma unroll 1
    for (int pass = 0; pass < 2; ++pass) {
        float* dst = (pass ? g_distT : g_distP) + b * IMG;

        // ---- load image into padded smem (float4 global reads) ----
        if (pass == 0) {
            const float4* s4 = (const float4*)P;
            for (int i = tid; i < IMG / 4; i += 256) {
                float4 v = s4[i];
                int base = i * 4;
                int y = base >> 7, x = base & 127;
                float* r = img + y * SM_STRIDE + x;
                r[0] = v.x; r[1] = v.y; r[2] = v.z; r[3] = v.w;
            }
        } else {
            // second pass: load target, fuse wmse accumulation (needs raw p & t)
            const float4* p4 = (const float4*)P;
            const float4* t4 = (const float4*)T;
            for (int i = tid; i < IMG / 4; i += 256) {
                float4 pv = p4[i];
                float4 tv = t4[i];
                int base = i * 4;
                int y = base >> 7, x = base & 127;
                float* r = img + y * SM_STRIDE + x;
                r[0] = tv.x; r[1] = tv.y; r[2] = tv.z; r[3] = tv.w;
                float pp[4] = {pv.x, pv.y, pv.z, pv.w};
                float tt[4] = {tv.x, tv.y, tv.z, tv.w};
                #pragma unroll
                for (int k = 0; k < 4; ++k) {
                    float t = tt[k];
                    float w = 1.0f;
                    if (t >= 0.5f)  w = 2.0f;
                    if (t >= 2.0f)  w = 5.0f;
                    if (t >= 5.0f)  w = 10.0f;
                    if (t >= 10.0f) w = 30.0f;
                    float d = pp[k] - t;
                    wsum += w * d * d;
                }
            }
        }
        __syncthreads();

        // ---- horizontal box sum: one thread per row, sliding window ----
        if (tid < IMG_H) {
            const float* row  = img + tid * SM_STRIDE;
            float*       hrow = hs  + tid * SM_STRIDE;
            float s = row[0] + row[1] + row[2] + row[3] + row[4];
            #pragma unroll 4
            for (int x = 0; x < IMG_W; ++x) {
                hrow[x] = s;
                if (x + 5 < IMG_W) s += row[x + 5];
                if (x - 4 >= 0)    s -= row[x - 4];
            }
        }
        __syncthreads();

        // ---- vertical box sum + distance: one thread per column ----
        if (tid < IMG_W) {
            const int x  = tid;
            const int cx = min(x + 4, IMG_W - 1) - max(x - 4, 0) + 1;
            float s = hs[0 * SM_STRIDE + x] + hs[1 * SM_STRIDE + x] +
                      hs[2 * SM_STRIDE + x] + hs[3 * SM_STRIDE + x] +
                      hs[4 * SM_STRIDE + x];
            #pragma unroll 4
            for (int y = 0; y < IMG_H; ++y) {
                int cy = min(y + 4, IMG_H - 1) - max(y - 4, 0) + 1;
                float mean = s / (float)(cx * cy);
                float d = img[y * SM_STRIDE + x] - mean;
                dst[y * IMG_W + x] = d;
                mn = fminf(mn, d);
                mx = fmaxf(mx, d);
                if (y + 5 < IMG_H) s += hs[(y + 5) * SM_STRIDE + x];
                if (y - 4 >= 0)    s -= hs[(y - 4) * SM_STRIDE + x];
            }
        }
        __syncthreads();   // protect img/hs reuse in next pass
    }

    // ---- deterministic block reduction (fixed tree) ----
    __shared__ float rmn[256], rmx[256], rws[256];
    rmn[tid] = mn; rmx[tid] = mx; rws[tid] = wsum;
    __syncthreads();
    #pragma unroll
    for (int s = 128; s > 0; s >>= 1) {
        if (tid < s) {
            rmn[tid] = fminf(rmn[tid], rmn[tid + s]);
            rmx[tid] = fmaxf(rmx[tid], rmx[tid + s]);
            rws[tid] += rws[tid + s];
        }
        __syncthreads();
    }
    if (tid == 0) { g_mn[b] = rmn[0]; g_mx[b] = rmx[0]; g_ws[b] = rws[0]; }
}

// ---------------------------------------------------------------------------
// k2: fold 4 partials -> lo, dx, wmse
// ---------------------------------------------------------------------------
__global__ void k2_fold() {
    float mn = INFINITY, mx = -INFINITY, ws = 0.0f;
    #pragma unroll
    for (int i = 0; i < NB; ++i) {
        mn = fminf(mn, g_mn[i]);
        mx = fmaxf(mx, g_mx[i]);
        ws += g_ws[i];
    }
    g_lo   = mn;
    g_dx   = (mx - mn) / (float)(NINT - 1);
    g_wmse = ws / (float)NPIX;
}

// ---------------------------------------------------------------------------
// k3: CRPS grid-point counts per pixel (O(1) each, integer partials)
// count = #{ j in [0,1000) : x_j in [min(p,t), max(p,t)) },  x_j = lo + j*dx
// ---------------------------------------------------------------------------
__global__ void k3_crps() {
    const float lo = g_lo;
    const float dx = g_dx;
    int cnt = 0;
    for (int i = blockIdx.x * blockDim.x + threadIdx.x; i < NPIX;
         i += gridDim.x * blockDim.x) {
        float p = g_distP[i];
        float t = g_distT[i];
        float a = fminf(p, t);
        float b = fmaxf(p, t);
        int ja = (int)ceilf((a - lo) / dx);   // #{j : x_j < a}
        int jb = (int)ceilf((b - lo) / dx);   // #{j : x_j < b}
        ja = min(max(ja, 0), NINT);
        jb = min(max(jb, 0), NINT);
        cnt += jb - ja;
    }
    __shared__ int sc[256];
    sc[threadIdx.x] = cnt;
    __syncthreads();
    #pragma unroll
    for (int s = 128; s > 0; s >>= 1) {
        if (threadIdx.x < s) sc[threadIdx.x] += sc[threadIdx.x + s];
        __syncthreads();
    }
    if (threadIdx.x == 0) g_cnt[blockIdx.x] = sc[0];
}

// ---------------------------------------------------------------------------
// k4: combine -> out[0] = 1e-4 * wmse + crps
// ---------------------------------------------------------------------------
__global__ void k4_final(float* __restrict__ out) {
    long long s = 0;
    #pragma unroll
    for (int i = 0; i < K3_BLOCKS; ++i) s += (long long)g_cnt[i];
    float crps = (float)((double)s * (double)g_dx / (double)NPIX);
    out[0] = 1e-4f * g_wmse + crps;
}

// ---------------------------------------------------------------------------
extern "C" void kernel_launch(void* const* d_in, const int* in_sizes, int n_in,
                              void* d_out, int out_size) {
    (void)in_sizes; (void)n_in; (void)out_size;
    const float* pred = (const float*)d_in[0];
    const float* tgt  = (const float*)d_in[1];
    float* out = (float*)d_out;

    cudaFuncSetAttribute(k1_dist, cudaFuncAttributeMaxDynamicSharedMemorySize,
                         (int)SMEM_BYTES);

    k1_dist<<<NB, 256, SMEM_BYTES>>>(pred, tgt);
    k2_fold<<<1, 1>>>();
    k3_crps<<<K3_BLOCKS, 256>>>();
    k4_final<<<1, 1>>>(out);
}

// round 2
// speedup vs baseline: 3.7097x; 3.7097x over previous
#include <cuda_runtime.h>
#include <math.h>

#define IMG_H   128
#define IMG_W   128
#define NB      4
#define IMG     (IMG_H * IMG_W)          // 16384
#define NPIX    (NB * IMG)               // 65536
#define NINT    1000
#define STRIPS  8
#define SROWS   16                       // output rows per strip
#define GBLK    (NB * STRIPS * 2)        // 64 blocks (4 img x 8 strips x {pred,tgt})
#define THREADS 256
#define ST      129                      // padded smem row stride
#define MAXR    24                       // 16 + 4 halo each side

// Static device scratch (no allocations allowed)
__device__ float g_distP[NPIX];
__device__ float g_distT[NPIX];
__device__ float g_mn[GBLK], g_mx[GBLK], g_ws[GBLK];
__device__ int   g_cnt[GBLK];
__device__ unsigned g_bar;               // monotonic ticket counter (never reset)

// Replay-safe grid barrier: epoch derived from ticket value, so the counter
// never needs resetting across graph replays. All GBLK blocks are co-resident.
__device__ __forceinline__ void grid_sync(int tid) {
    __syncthreads();
    if (tid == 0) {
        __threadfence();
        unsigned t   = atomicAdd(&g_bar, 1u);
        unsigned tgt = (t / (unsigned)GBLK + 1u) * (unsigned)GBLK;
        while (*(volatile unsigned*)&g_bar < tgt) { }
        __threadfence();
    }
    __syncthreads();
}

__global__ void __launch_bounds__(THREADS, 1)
fused_loss(const float* __restrict__ pred, const float* __restrict__ tgt,
           float* __restrict__ out) {
    __shared__ float img[MAXR * ST];
    __shared__ float hs [MAXR * ST];
    __shared__ float red[2 * THREADS];
    __shared__ int   sci[THREADS];

    const int tid    = threadIdx.x;
    const int b      = blockIdx.x;
    const int tensor = b & 1;
    const int strip  = (b >> 1) & 7;
    const int im     = b >> 4;

    const float* src = (tensor ? tgt : pred) + im * IMG;
    float*       dst = (tensor ? g_distT : g_distP) + im * IMG;

    const int y0 = strip * SROWS;
    const int lo = max(0, y0 - 4);
    const int hi = min(IMG_H, y0 + SROWS + 4);
    const int nrows = hi - lo;

    // ---------------- Phase 1: box-mean distances for this strip ----------
    // load strip + halo into padded smem (float4)
    {
        const float4* s4 = (const float4*)(src + lo * IMG_W);
        const int n4 = nrows * (IMG_W / 4);
        for (int i = tid; i < n4; i += THREADS) {
            float4 v = s4[i];
            int base = i * 4;
            int r = base >> 7, x = base & 127;
            float* p = img + r * ST + x;
            p[0] = v.x; p[1] = v.y; p[2] = v.z; p[3] = v.w;
        }
    }
    __syncthreads();

    // horizontal sliding box sum, 4 segments per row (32 serial iters each)
    if (tid < nrows * 4) {
        const int r = tid >> 2, h = tid & 3;
        const float* row  = img + r * ST;
        float*       hrow = hs  + r * ST;
        const int x0 = h * 32;
        float s = 0.0f;
        for (int xx = max(0, x0 - 4); xx <= x0 + 4; ++xx) s += row[xx];
        #pragma unroll 4
        for (int x = x0; x < x0 + 32; ++x) {
            hrow[x] = s;
            if (x + 5 < IMG_W) s += row[x + 5];
            if (x - 4 >= 0)    s -= row[x - 4];
        }
    }
    __syncthreads();

    // vertical sliding box sum + distance, 2 segments per column (8 iters)
    float mn = INFINITY, mx = -INFINITY;
    {
        const int x   = tid & 127;
        const int seg = tid >> 7;          // 0 or 1
        const int oy0 = seg * 8;
        const int cx  = min(x + 4, IMG_W - 1) - max(x - 4, 0) + 1;
        const int yb  = y0 + oy0;
        float s = 0.0f;
        const int wlo = max(0, yb - 4), whi = min(IMG_H - 1, yb + 4);
        for (int yy = wlo; yy <= whi; ++yy) s += hs[(yy - lo) * ST + x];
        #pragma unroll
        for (int oy = oy0; oy < oy0 + 8; ++oy) {
            const int y  = y0 + oy;
            const int cy = min(y + 4, IMG_H - 1) - max(y - 4, 0) + 1;
            const float mean = s / (float)(cx * cy);
            const float d = img[(y - lo) * ST + x] - mean;
            dst[y * IMG_W + x] = d;
            mn = fminf(mn, d);
            mx = fmaxf(mx, d);
            if (oy < oy0 + 7) {
                if (y + 5 < IMG_H) s += hs[(y + 5 - lo) * ST + x];
                if (y - 4 >= 0)    s -= hs[(y - 4 - lo) * ST + x];
            }
        }
    }

    // deterministic block reduction of min/max
    red[tid] = mn; red[THREADS + tid] = mx;
    __syncthreads();
    #pragma unroll
    for (int s = 128; s > 0; s >>= 1) {
        if (tid < s) {
            red[tid]           = fminf(red[tid], red[tid + s]);
            red[THREADS + tid] = fmaxf(red[THREADS + tid], red[THREADS + tid + s]);
        }
        __syncthreads();
    }
    if (tid == 0) { g_mn[b] = red[0]; g_mx[b] = red[THREADS]; }

    grid_sync(tid);

    // ---------------- Phase 2: fold lo/dx, CRPS counts + wmse -------------
    if (tid < GBLK) { red[tid] = g_mn[tid]; red[THREADS + tid] = g_mx[tid]; }
    __syncthreads();
    #pragma unroll
    for (int s = 32; s > 0; s >>= 1) {
        if (tid < s) {
            red[tid]           = fminf(red[tid], red[tid + s]);
            red[THREADS + tid] = fmaxf(red[THREADS + tid], red[THREADS + tid + s]);
        }
        __syncthreads();
    }
    const float flo = red[0];
    const float fdx = (red[THREADS] - red[0]) / (float)(NINT - 1);
    __syncthreads();   // done reading red before reuse

    // CRPS: count = #{ j in [0,NINT) : x_j in [min(p,t), max(p,t)) },
    // x_j = lo + j*dx.  Integer per pixel -> exact deterministic sum.
    int   cnt  = 0;
    float wsum = 0.0f;
    const int base = b * (NPIX / GBLK);   // 1024 pixels per block
    #pragma unroll
    for (int k = 0; k < (NPIX / GBLK) / THREADS; ++k) {
        const int i = base + k * THREADS + tid;
        const float dp = __ldcg(&g_distP[i]);
        const float dt = __ldcg(&g_distT[i]);
        const float a = fminf(dp, dt);
        const float c = fmaxf(dp, dt);
        int ja = (int)ceilf((a - flo) / fdx);
        int jb = (int)ceilf((c - flo) / fdx);
        ja = min(max(ja, 0), NINT);
        jb = min(max(jb, 0), NINT);
        cnt += jb - ja;

        const float p = pred[i], t = tgt[i];
        float w = 1.0f;
        if (t >= 0.5f)  w = 2.0f;
        if (t >= 2.0f)  w = 5.0f;
        if (t >= 5.0f)  w = 10.0f;
        if (t >= 10.0f) w = 30.0f;
        const float dd = p - t;
        wsum += w * dd * dd;
    }

    sci[tid] = cnt; red[tid] = wsum;
    __syncthreads();
    #pragma unroll
    for (int s = 128; s > 0; s >>= 1) {
        if (tid < s) { sci[tid] += sci[tid + s]; red[tid] += red[tid + s]; }
        __syncthreads();
    }
    if (tid == 0) { g_cnt[b] = sci[0]; g_ws[b] = red[0]; }

    grid_sync(tid);

    // ---------------- Phase 3: final combine (block 0 only) ---------------
    if (b == 0) {
        if (tid < GBLK) { sci[tid] = g_cnt[tid]; red[tid] = g_ws[tid]; }
        __syncthreads();
        #pragma unroll
        for (int s = 32; s > 0; s >>= 1) {
            if (tid < s) { sci[tid] += sci[tid + s]; red[tid] += red[tid + s]; }
            __syncthreads();
        }
        if (tid == 0) {
            const float wmse = red[0] / (float)NPIX;
            const float crps = (float)((double)sci[0] * (double)fdx / (double)NPIX);
            out[0] = 1e-4f * wmse + crps;
        }
    }
}

extern "C" void kernel_launch(void* const* d_in, const int* in_sizes, int n_in,
                              void* d_out, int out_size) {
    (void)in_sizes; (void)n_in; (void)out_size;
    const float* pred = (const float*)d_in[0];
    const float* tgt  = (const float*)d_in[1];
    float* out = (float*)d_out;

    fused_loss<<<GBLK, THREADS>>>(pred, tgt, out);
}

// round 3
// speedup vs baseline: 4.3885x; 1.1830x over previous
#include <cuda_runtime.h>
#include <math.h>

#define IMG_H   128
#define IMG_W   128
#define NB      4
#define IMG     (IMG_H * IMG_W)          // 16384
#define NPIX    (NB * IMG)               // 65536
#define NINT    1000
#define STRIPS  16
#define SROWS   8                        // output rows per strip
#define GBLK    (NB * STRIPS)            // 64 blocks (4 img x 16 strips, BOTH tensors)
#define THREADS 256
#define ST      129                      // padded smem row stride
#define MAXR    16                       // 8 + 4 halo each side

// Static device scratch (no allocations allowed)
__device__ float g_mn[GBLK], g_mx[GBLK], g_ws[GBLK];
__device__ int   g_cnt[GBLK];
__device__ unsigned g_bar1;              // grid barrier ticket (monotonic)
__device__ unsigned g_bar2;              // last-block ticket (monotonic)

// Replay-safe grid barrier: epoch derived from ticket value (never reset).
__device__ __forceinline__ void grid_sync(int tid) {
    __syncthreads();
    if (tid == 0) {
        __threadfence();
        unsigned t   = atomicAdd(&g_bar1, 1u);
        unsigned tgt = (t / (unsigned)GBLK + 1u) * (unsigned)GBLK;
        while (*(volatile unsigned*)&g_bar1 < tgt) { }
        __threadfence();
    }
    __syncthreads();
}

__global__ void __launch_bounds__(THREADS, 1)
fused_loss(const float* __restrict__ pred, const float* __restrict__ tgt,
           float* __restrict__ out) {
    __shared__ float imgA[MAXR * ST];    // pred strip
    __shared__ float imgB[MAXR * ST];    // tgt strip
    __shared__ float hs  [MAXR * ST];    // horizontal sums (reused per tensor)
    __shared__ float red [2 * THREADS];
    __shared__ int   sci [THREADS];

    const int tid   = threadIdx.x;
    const int b     = blockIdx.x;
    const int im    = b >> 4;
    const int strip = b & 15;

    const int y0 = strip * SROWS;
    const int lo = max(0, y0 - 4);
    const int hi = min(IMG_H, y0 + SROWS + 4);
    const int nrows = hi - lo;

    // ---- load both strips (float4), fuse wmse on strip-owned rows --------
    float wsum = 0.0f;
    {
        const float4* p4 = (const float4*)(pred + (im * IMG + lo * IMG_W));
        const float4* t4 = (const float4*)(tgt  + (im * IMG + lo * IMG_W));
        const int n4 = nrows * (IMG_W / 4);
        for (int i = tid; i < n4; i += THREADS) {
            float4 pv = p4[i];
            float4 tv = t4[i];
            int base = i * 4;
            int r = base >> 7, x = base & 127;
            float* pa = imgA + r * ST + x;
            float* pb = imgB + r * ST + x;
            pa[0] = pv.x; pa[1] = pv.y; pa[2] = pv.z; pa[3] = pv.w;
            pb[0] = tv.x; pb[1] = tv.y; pb[2] = tv.z; pb[3] = tv.w;
            const int gy = lo + r;
            if (gy >= y0 && gy < y0 + SROWS) {
                float pp[4] = {pv.x, pv.y, pv.z, pv.w};
                float tt[4] = {tv.x, tv.y, tv.z, tv.w};
                #pragma unroll
                for (int k = 0; k < 4; ++k) {
                    float t = tt[k];
                    float w = 1.0f;
                    if (t >= 0.5f)  w = 2.0f;
                    if (t >= 2.0f)  w = 5.0f;
                    if (t >= 5.0f)  w = 10.0f;
                    if (t >= 10.0f) w = 30.0f;
                    float d = pp[k] - t;
                    wsum += w * d * d;
                }
            }
        }
    }
    __syncthreads();

    // ---- separable 9-tap edge-corrected box filter, dist kept in regs ----
    // Each thread owns pixels: column x = tid&127, rows y0+seg*4 .. +3.
    const int x   = tid & 127;
    const int seg = tid >> 7;            // 0 or 1
    const int oy0 = seg * 4;
    const int cx  = min(x + 4, IMG_W - 1) - max(x - 4, 0) + 1;

    float dreg[2][4];
    float mn = INFINITY, mx = -INFINITY;

    #pragma unroll
    for (int pass = 0; pass < 2; ++pass) {
        const float* img = pass ? imgB : imgA;

        // horizontal sliding sums: 16 segments of 8 per row (256 tasks)
        if (tid < nrows * 16) {
            const int r  = tid >> 4;
            const int x0 = (tid & 15) * 8;
            const float* row  = img + r * ST;
            float*       hrow = hs  + r * ST;
            float s = 0.0f;
            #pragma unroll
            for (int dx = -4; dx <= 4; ++dx) {
                int xx = x0 + dx;
                if (xx >= 0 && xx < IMG_W) s += row[xx];
            }
            #pragma unroll
            for (int k = 0; k < 8; ++k) {
                const int xc = x0 + k;
                hrow[xc] = s;
                if (xc + 5 < IMG_W) s += row[xc + 5];
                if (xc - 4 >= 0)    s -= row[xc - 4];
            }
        }
        __syncthreads();

        // vertical sliding sums + distance (4 rows per thread, in regs)
        {
            const int yb = y0 + oy0;
            float s = 0.0f;
            const int wlo = max(0, yb - 4), whi = min(IMG_H - 1, yb + 4);
            for (int yy = wlo; yy <= whi; ++yy) s += hs[(yy - lo) * ST + x];
            #pragma unroll
            for (int k = 0; k < 4; ++k) {
                const int y  = yb + k;
                const int cy = min(y + 4, IMG_H - 1) - max(y - 4, 0) + 1;
                const float mean = s / (float)(cx * cy);
                const float d = img[(y - lo) * ST + x] - mean;
                dreg[pass][k] = d;
                mn = fminf(mn, d);
                mx = fmaxf(mx, d);
                if (k < 3) {
                    if (y + 5 < IMG_H) s += hs[(y + 5 - lo) * ST + x];
                    if (y - 4 >= 0)    s -= hs[(y - 4 - lo) * ST + x];
                }
            }
        }
        __syncthreads();   // hs reuse next pass
    }

    // ---- block reduce min/max (deterministic tree), publish partials -----
    red[tid] = mn; red[THREADS + tid] = mx;
    __syncthreads();
    #pragma unroll
    for (int s = 128; s > 0; s >>= 1) {
        if (tid < s) {
            red[tid]           = fminf(red[tid], red[tid + s]);
            red[THREADS + tid] = fmaxf(red[THREADS + tid], red[THREADS + tid + s]);
        }
        __syncthreads();
    }
    if (tid == 0) { g_mn[b] = red[0]; g_mx[b] = red[THREADS]; g_ws[b] = 0.0f; }

    grid_sync(tid);

    // ---- fold global lo/dx (every block, from 64 scalars in L2) ----------
    if (tid < GBLK) { red[tid] = g_mn[tid]; red[THREADS + tid] = g_mx[tid]; }
    __syncthreads();
    #pragma unroll
    for (int s = 32; s > 0; s >>= 1) {
        if (tid < s) {
            red[tid]           = fminf(red[tid], red[tid + s]);
            red[THREADS + tid] = fmaxf(red[THREADS + tid], red[THREADS + tid + s]);
        }
        __syncthreads();
    }
    const float flo = red[0];
    const float fdx = (red[THREADS] - red[0]) / (float)(NINT - 1);
    __syncthreads();

    // ---- CRPS counts from register-resident dist pairs (exact ints) ------
    // count = #{ j in [0,NINT) : x_j in [min(dp,dt), max(dp,dt)) }, x_j=lo+j*dx
    int cnt = 0;
    #pragma unroll
    for (int k = 0; k < 4; ++k) {
        const float a = fminf(dreg[0][k], dreg[1][k]);
        const float c = fmaxf(dreg[0][k], dreg[1][k]);
        int ja = (int)ceilf((a - flo) / fdx);
        int jb = (int)ceilf((c - flo) / fdx);
        ja = min(max(ja, 0), NINT);
        jb = min(max(jb, 0), NINT);
        cnt += jb - ja;
    }

    sci[tid] = cnt; red[tid] = wsum;
    __syncthreads();
    #pragma unroll
    for (int s = 128; s > 0; s >>= 1) {
        if (tid < s) { sci[tid] += sci[tid + s]; red[tid] += red[tid + s]; }
        __syncthreads();
    }

    // ---- last block to arrive performs the final fold (no 2nd barrier) ---
    __shared__ int is_last;
    if (tid == 0) {
        g_cnt[b] = sci[0];
        g_ws[b]  = red[0];
        __threadfence();
        unsigned t = atomicAdd(&g_bar2, 1u);
        is_last = ((t % (unsigned)GBLK) == (unsigned)(GBLK - 1));
    }
    __syncthreads();

    if (is_last) {
        if (tid == 0) __threadfence();
        __syncthreads();
        if (tid < GBLK) { sci[tid] = g_cnt[tid]; red[tid] = g_ws[tid]; }
        else            { sci[tid] = 0;          red[tid] = 0.0f;      }
        __syncthreads();
        #pragma unroll
        for (int s = 32; s > 0; s >>= 1) {
            if (tid < s) { sci[tid] += sci[tid + s]; red[tid] += red[tid + s]; }
            __syncthreads();
        }
        if (tid == 0) {
            const float wmse = red[0] / (float)NPIX;
            const float crps = (float)((double)sci[0] * (double)fdx / (double)NPIX);
            out[0] = 1e-4f * wmse + crps;
        }
    }
}

extern "C" void kernel_launch(void* const* d_in, const int* in_sizes, int n_in,
                              void* d_out, int out_size) {
    (void)in_sizes; (void)n_in; (void)out_size;
    const float* pred = (const float*)d_in[0];
    const float* tgt  = (const float*)d_in[1];
    float* out = (float*)d_out;

    fused_loss<<<GBLK, THREADS>>>(pred, tgt, out);
}